// round 9
// baseline (speedup 1.0000x reference)
#include <cuda_runtime.h>

#define S_TOT 4096
#define N_OBJ 32
#define H_D   64
#define PT    34   // transposed stride: bank (2k+lane)%32, conflict-free per lane
#define PA    68   // row-major a stride (floats); PA = 2*PT so regions coincide
#define NPAIR 496
#define SAMP_F (H_D * PT)   // 2176 floats per sample region (= 32*68)

typedef unsigned long long u64;

__device__ __forceinline__ u64 pack2(float lo, float hi) {
    u64 r; asm("mov.b64 %0, {%1, %2};" : "=l"(r) : "f"(lo), "f"(hi)); return r;
}
__device__ __forceinline__ void unpack2(u64 v, float& lo, float& hi) {
    asm("mov.b64 {%0, %1}, %2;" : "=f"(lo), "=f"(hi) : "l"(v));
}
__device__ __forceinline__ u64 ffma2(u64 a, u64 b, u64 c) {
    u64 d; asm("fma.rn.f32x2 %0, %1, %2, %3;" : "=l"(d) : "l"(a), "l"(b), "l"(c)); return d;
}
__device__ __forceinline__ float tanh_fast(float x) {   // 1 MUFU
    float y; asm("tanh.approx.f32 %0, %1;" : "=f"(y) : "f"(x)); return y;
}
__device__ __forceinline__ int rb(int x) { return x * 31 - ((x * (x - 1)) >> 1); }

__global__ __launch_bounds__(256, 4)
void magnet_main(const float* __restrict__ X,     // [S,32,4]
                 const float* __restrict__ L1W,   // [64,4]
                 const float* __restrict__ L1b,   // [64]
                 const float* __restrict__ L2W,   // [64,64]
                 const float* __restrict__ L2b,   // [64]
                 const float* __restrict__ I1W,   // [64,64]
                 const float* __restrict__ I2W,   // [8,64]
                 const float* __restrict__ I3,    // [992,2,4]
                 const float* __restrict__ S1W,   // [4,4]
                 const float* __restrict__ S1b,   // [4]
                 const float* __restrict__ S2W,   // [32,2,2]
                 const float* __restrict__ S2b,   // [32,2]
                 float* __restrict__ out)         // [S,32,2]
{
    // 2 samples per block
    __shared__ __align__(16) float bufT1[2 * SAMP_F];       // h1 [s][k][PT]; reused: a [s][obj][PA]
    __shared__ __align__(16) float bufT2_sPair[2 * SAMP_F]; // h2 [s][k][PT]; alias: sPair [s][496][4]
    __shared__ __align__(16) float sW[H_D * H_D];           // L2W then I1W (row-major [c][k])
    __shared__ __align__(16) float sI2[H_D * 8];            // [h][f]
    __shared__ __align__(16) float sX[2 * N_OBJ * 4];
    __shared__ __align__(16) float sL1W[H_D * 4];
    __shared__ float sL1b[H_D];
    __shared__ float sL2b[H_D];
    __shared__ float sRes[2 * N_OBJ * 2];

    float* bufT2 = bufT2_sPair;
    float* sPair = bufT2_sPair;

    const int tid  = threadIdx.x;
    const int bid  = blockIdx.x;
    const int wS   = tid >> 5;       // warp 0..7
    const int lane = tid & 31;       // = object in encoder stages
    const int c0   = wS * 8;         // 8 channels per warp (warp-uniform)

    // ---- staging ----
    {
        const float4* W2 = (const float4*)L2W;
        #pragma unroll
        for (int q = 0; q < 4; q++)
            ((float4*)sW)[tid + q * 256] = __ldg(W2 + tid + q * 256);
        #pragma unroll
        for (int e = 0; e < 2; e++) {                 // sI2[h][f] = I2W[f][h]
            int idx = tid + e * 256;
            int h = idx >> 3, f = idx & 7;
            sI2[idx] = __ldg(I2W + f * 64 + h);
        }
        if (tid < 64)        ((float4*)sX)[tid]        = __ldg(((const float4*)X) + bid * 64 + tid);
        else if (tid < 128)  ((float4*)sL1W)[tid - 64] = __ldg(((const float4*)L1W) + (tid - 64));
        else if (tid < 192)  sL1b[tid - 128] = __ldg(L1b + tid - 128);
        else                 sL2b[tid - 192] = __ldg(L2b + tid - 192);
    }
    __syncthreads();

    // ---- stage 1: h1 = relu(x @ L1W^T + L1b), both samples -> bufT1 transposed ----
    {
        float4 x0 = ((const float4*)sX)[lane];
        float4 x1 = ((const float4*)sX)[N_OBJ + lane];
        #pragma unroll
        for (int q = 0; q < 8; q++) {
            int c = c0 + q;
            float4 w = ((const float4*)sL1W)[c];         // broadcast (both samples)
            float b = sL1b[c];
            float v0 = fmaf(x0.x, w.x, fmaf(x0.y, w.y, fmaf(x0.z, w.z, fmaf(x0.w, w.w, b))));
            float v1 = fmaf(x1.x, w.x, fmaf(x1.y, w.y, fmaf(x1.z, w.z, fmaf(x1.w, w.w, b))));
            bufT1[c * PT + lane]          = fmaxf(v0, 0.f);
            bufT1[SAMP_F + c * PT + lane] = fmaxf(v1, 0.f);
        }
    }
    // ---- self term (64 threads = 2 samples x 32 obj) -> sRes ----
    if (tid < 64) {
        int o = tid & 31;
        float4 xv = ((const float4*)sX)[tid];
        float hs[4];
        #pragma unroll
        for (int f = 0; f < 4; f++) {
            float4 w = __ldg(((const float4*)S1W) + f);
            hs[f] = fmaxf(xv.x*w.x + xv.y*w.y + xv.z*w.z + xv.w*w.w + __ldg(S1b + f), 0.f);
        }
        float4 s2 = __ldg(((const float4*)S2W) + o);
        sRes[tid * 2 + 0] = hs[0] * s2.x + hs[1] * s2.y + __ldg(S2b + o * 2 + 0);
        sRes[tid * 2 + 1] = hs[2] * s2.z + hs[3] * s2.w + __ldg(S2b + o * 2 + 1);
    }
    __syncthreads();

    // ---- stage 2: h2 = relu(h1 @ L2W^T + L2b), both samples -> bufT2 ----
    {
        u64 acc0[8], acc1[8];
        #pragma unroll
        for (int q = 0; q < 8; q++) { acc0[q] = pack2(sL2b[c0 + q], 0.f); acc1[q] = acc0[q]; }
        #pragma unroll
        for (int k4 = 0; k4 < 16; k4++) {
            int kb = k4 * 4;
            float p0 = bufT1[(kb + 0) * PT + lane];
            float p1 = bufT1[(kb + 1) * PT + lane];
            float p2 = bufT1[(kb + 2) * PT + lane];
            float p3 = bufT1[(kb + 3) * PT + lane];
            float q0 = bufT1[SAMP_F + (kb + 0) * PT + lane];
            float q1 = bufT1[SAMP_F + (kb + 1) * PT + lane];
            float q2 = bufT1[SAMP_F + (kb + 2) * PT + lane];
            float q3 = bufT1[SAMP_F + (kb + 3) * PT + lane];
            u64 hA0 = pack2(p0, p1), hA1 = pack2(p2, p3);
            u64 hB0 = pack2(q0, q1), hB1 = pack2(q2, q3);
            #pragma unroll
            for (int q = 0; q < 8; q++) {
                ulonglong2 w = *(const ulonglong2*)&sW[(c0 + q) * 64 + kb];  // 1 bcast, 2 samples
                acc0[q] = ffma2(hA0, w.x, acc0[q]); acc0[q] = ffma2(hA1, w.y, acc0[q]);
                acc1[q] = ffma2(hB0, w.x, acc1[q]); acc1[q] = ffma2(hB1, w.y, acc1[q]);
            }
        }
        #pragma unroll
        for (int q = 0; q < 8; q++) {
            float lo, hi;
            unpack2(acc0[q], lo, hi); bufT2[(c0 + q) * PT + lane]          = fmaxf(lo + hi, 0.f);
            unpack2(acc1[q], lo, hi); bufT2[SAMP_F + (c0 + q) * PT + lane] = fmaxf(lo + hi, 0.f);
        }
    }
    __syncthreads();

    // ---- restage: sW <- I1W ----
    {
        const float4* W1 = (const float4*)I1W;
        #pragma unroll
        for (int q = 0; q < 4; q++)
            ((float4*)sW)[tid + q * 256] = __ldg(W1 + tid + q * 256);
    }
    __syncthreads();

    // ---- stage 3: a = h2 @ I1W^T -> bufT1 reused ROW-MAJOR a[s][obj][PA] ----
    {
        u64 acc0[8] = {0,0,0,0,0,0,0,0}, acc1[8] = {0,0,0,0,0,0,0,0};
        #pragma unroll
        for (int k4 = 0; k4 < 16; k4++) {
            int kb = k4 * 4;
            float p0 = bufT2[(kb + 0) * PT + lane];
            float p1 = bufT2[(kb + 1) * PT + lane];
            float p2 = bufT2[(kb + 2) * PT + lane];
            float p3 = bufT2[(kb + 3) * PT + lane];
            float q0 = bufT2[SAMP_F + (kb + 0) * PT + lane];
            float q1 = bufT2[SAMP_F + (kb + 1) * PT + lane];
            float q2 = bufT2[SAMP_F + (kb + 2) * PT + lane];
            float q3 = bufT2[SAMP_F + (kb + 3) * PT + lane];
            u64 hA0 = pack2(p0, p1), hA1 = pack2(p2, p3);
            u64 hB0 = pack2(q0, q1), hB1 = pack2(q2, q3);
            #pragma unroll
            for (int q = 0; q < 8; q++) {
                ulonglong2 w = *(const ulonglong2*)&sW[(c0 + q) * 64 + kb];
                acc0[q] = ffma2(hA0, w.x, acc0[q]); acc0[q] = ffma2(hA1, w.y, acc0[q]);
                acc1[q] = ffma2(hB0, w.x, acc1[q]); acc1[q] = ffma2(hB1, w.y, acc1[q]);
            }
        }
        float4 o; float lo, hi;
        unpack2(acc0[0], lo, hi); o.x = lo + hi;
        unpack2(acc0[1], lo, hi); o.y = lo + hi;
        unpack2(acc0[2], lo, hi); o.z = lo + hi;
        unpack2(acc0[3], lo, hi); o.w = lo + hi;
        *(float4*)&bufT1[lane * PA + c0] = o;
        unpack2(acc0[4], lo, hi); o.x = lo + hi;
        unpack2(acc0[5], lo, hi); o.y = lo + hi;
        unpack2(acc0[6], lo, hi); o.z = lo + hi;
        unpack2(acc0[7], lo, hi); o.w = lo + hi;
        *(float4*)&bufT1[lane * PA + c0 + 4] = o;
        unpack2(acc1[0], lo, hi); o.x = lo + hi;
        unpack2(acc1[1], lo, hi); o.y = lo + hi;
        unpack2(acc1[2], lo, hi); o.z = lo + hi;
        unpack2(acc1[3], lo, hi); o.w = lo + hi;
        *(float4*)&bufT1[SAMP_F + lane * PA + c0] = o;
        unpack2(acc1[4], lo, hi); o.x = lo + hi;
        unpack2(acc1[5], lo, hi); o.y = lo + hi;
        unpack2(acc1[6], lo, hi); o.z = lo + hi;
        unpack2(acc1[7], lo, hi); o.w = lo + hi;
        *(float4*)&bufT1[SAMP_F + lane * PA + c0 + 4] = o;
    }
    __syncthreads();

    // ---- pair stage: unit = (i, j0, j1), same unit for both samples ----
    {
        int i = 0, base = 0;
        while (tid >= base + ((32 - i) >> 1)) { base += (32 - i) >> 1; ++i; }
        const int u  = tid - base;
        const int nu = (32 - i) >> 1;
        const int j0 = i + 1 + u;
        const int j1 = j0 + nu;
        const bool has2 = (j1 <= 31);
        const int j1c = has2 ? j1 : j0;

        const float4* A = (const float4*)bufT1;      // rows of 17 float4; sample 1 at +544
        const float4* ai0  = A + i * 17;
        const float4* aj00 = A + j0 * 17;
        const float4* aj01 = A + j1c * 17;
        const float4* ai1  = A + 544 + i * 17;
        const float4* aj10 = A + 544 + j0 * 17;
        const float4* aj11 = A + 544 + j1c * 17;

        u64 P[4][4] = {};   // [s0p0, s0p1, s1p0, s1p1][feature-pair]
        #pragma unroll
        for (int k4 = 0; k4 < 16; k4++) {
            float4 x0 = ai0[k4], y00 = aj00[k4], y01 = aj01[k4];
            float4 x1 = ai1[k4], y10 = aj10[k4], y11 = aj11[k4];
            const float* fx0 = (const float*)&x0;
            const float* f00 = (const float*)&y00;
            const float* f01 = (const float*)&y01;
            const float* fx1 = (const float*)&x1;
            const float* f10 = (const float*)&y10;
            const float* f11 = (const float*)&y11;
            #pragma unroll
            for (int v = 0; v < 4; v++) {
                float t0 = tanh_fast(fx0[v] - f00[v]);
                float t1 = tanh_fast(fx0[v] - f01[v]);
                float t2 = tanh_fast(fx1[v] - f10[v]);
                float t3 = tanh_fast(fx1[v] - f11[v]);
                const ulonglong2* wp = (const ulonglong2*)&sI2[(k4 * 4 + v) * 8];
                ulonglong2 wa = wp[0], wb = wp[1];   // 1 bcast, 4 pair-instances
                u64 tt;
                tt = pack2(t0, t0);
                P[0][0] = ffma2(tt, wa.x, P[0][0]); P[0][1] = ffma2(tt, wa.y, P[0][1]);
                P[0][2] = ffma2(tt, wb.x, P[0][2]); P[0][3] = ffma2(tt, wb.y, P[0][3]);
                tt = pack2(t1, t1);
                P[1][0] = ffma2(tt, wa.x, P[1][0]); P[1][1] = ffma2(tt, wa.y, P[1][1]);
                P[1][2] = ffma2(tt, wb.x, P[1][2]); P[1][3] = ffma2(tt, wb.y, P[1][3]);
                tt = pack2(t2, t2);
                P[2][0] = ffma2(tt, wa.x, P[2][0]); P[2][1] = ffma2(tt, wa.y, P[2][1]);
                P[2][2] = ffma2(tt, wb.x, P[2][2]); P[2][3] = ffma2(tt, wb.y, P[2][3]);
                tt = pack2(t3, t3);
                P[3][0] = ffma2(tt, wa.x, P[3][0]); P[3][1] = ffma2(tt, wa.y, P[3][1]);
                P[3][2] = ffma2(tt, wb.x, P[3][2]); P[3][3] = ffma2(tt, wb.y, P[3][3]);
            }
        }

        const int rbi = rb(i);
        #pragma unroll
        for (int pp = 0; pp < 2; pp++) {
            if (pp == 1 && !has2) break;
            int j = pp ? j1 : j0;
            int idx_ij = i * 31 + (j - 1);
            int idx_ji = j * 31 + i;
            float4 gi0 = __ldg((const float4*)(I3 + idx_ij * 8));
            float4 gi1 = __ldg((const float4*)(I3 + idx_ij * 8) + 1);
            float4 gj0 = __ldg((const float4*)(I3 + idx_ji * 8));
            float4 gj1 = __ldg((const float4*)(I3 + idx_ji * 8) + 1);
            int p = rbi + (j - i - 1);
            #pragma unroll
            for (int s2 = 0; s2 < 2; s2++) {         // I3 loaded once, both samples
                int pi = s2 * 2 + pp;
                float t[8];
                unpack2(P[pi][0], t[0], t[1]); unpack2(P[pi][1], t[2], t[3]);
                unpack2(P[pi][2], t[4], t[5]); unpack2(P[pi][3], t[6], t[7]);
                #pragma unroll
                for (int f = 0; f < 8; f++) t[f] = tanh_fast(t[f]);
                float4 res;
                res.x = t[0]*gi0.x + t[1]*gi0.y + t[2]*gi0.z + t[3]*gi0.w;
                res.y = t[4]*gi1.x + t[5]*gi1.y + t[6]*gi1.z + t[7]*gi1.w;
                res.z = -(t[0]*gj0.x + t[1]*gj0.y + t[2]*gj0.z + t[3]*gj0.w);
                res.w = -(t[4]*gj1.x + t[5]*gj1.y + t[6]*gj1.z + t[7]*gj1.w);
                ((float4*)(sPair + s2 * NPAIR * 4))[p] = res;   // bufT2 region (dead)
            }
        }
    }
    __syncthreads();

    // ---- parallel deterministic reduction: 4 threads per (sample, object) ----
    {
        const int s2 = tid >> 7;          // sample
        const int o  = (tid >> 2) & 31;   // object
        const int q  = tid & 3;           // quarter
        const float2* sp2 = (const float2*)(sPair + s2 * NPAIR * 4);
        float a0 = 0.f, a1 = 0.f;
        const int nrow = 31 - o;          // row terms (j > o), then col terms
        for (int m = q; m < 31; m += 4) {
            int p, half;
            if (m < nrow) { p = rb(o) + m; half = 0; }
            else          { int k = m - nrow; p = rb(k) + (o - k - 1); half = 1; }
            float2 v = sp2[p * 2 + half];
            a0 += v.x; a1 += v.y;
        }
        a0 += __shfl_xor_sync(0xffffffffu, a0, 1);
        a1 += __shfl_xor_sync(0xffffffffu, a1, 1);
        a0 += __shfl_xor_sync(0xffffffffu, a0, 2);
        a1 += __shfl_xor_sync(0xffffffffu, a1, 2);
        if (q == 0) {
            float2 r;
            r.x = a0 + sRes[(s2 * N_OBJ + o) * 2 + 0];
            r.y = a1 + sRes[(s2 * N_OBJ + o) * 2 + 1];
            ((float2*)out)[(bid * 2 + s2) * N_OBJ + o] = r;
        }
    }
}

extern "C" void kernel_launch(void* const* d_in, const int* in_sizes, int n_in,
                              void* d_out, int out_size) {
    const float* inputs = (const float*)d_in[0];
    const float* L1W    = (const float*)d_in[1];
    const float* L1b    = (const float*)d_in[2];
    const float* L2W    = (const float*)d_in[3];
    const float* L2b    = (const float*)d_in[4];
    const float* I1W    = (const float*)d_in[5];
    const float* I2W    = (const float*)d_in[6];
    const float* I3     = (const float*)d_in[7];
    const float* S1W    = (const float*)d_in[8];
    const float* S1b    = (const float*)d_in[9];
    const float* S2W    = (const float*)d_in[10];
    const float* S2b    = (const float*)d_in[11];
    float* out = (float*)d_out;

    magnet_main<<<S_TOT / 2, 256>>>(inputs, L1W, L1b, L2W, L2b,
                                    I1W, I2W, I3, S1W, S1b, S2W, S2b, out);
}

// round 10
// speedup vs baseline: 1.1132x; 1.1132x over previous
#include <cuda_runtime.h>

#define S_TOT 4096
#define N_OBJ 32
#define H_D   64
#define PT    34   // transposed stride: bank (2k+lane)%32, conflict-free per lane
#define PA    68   // row-major a stride (floats); PA = 2*PT so regions coincide
#define NPAIR 496
#define SAMP_F (H_D * PT)   // 2176 floats per sample region (= 32*68)

typedef unsigned long long u64;

__device__ __forceinline__ u64 pack2(float lo, float hi) {
    u64 r; asm("mov.b64 %0, {%1, %2};" : "=l"(r) : "f"(lo), "f"(hi)); return r;
}
__device__ __forceinline__ void unpack2(u64 v, float& lo, float& hi) {
    asm("mov.b64 {%0, %1}, %2;" : "=f"(lo), "=f"(hi) : "l"(v));
}
__device__ __forceinline__ u64 ffma2(u64 a, u64 b, u64 c) {
    u64 d; asm("fma.rn.f32x2 %0, %1, %2, %3;" : "=l"(d) : "l"(a), "l"(b), "l"(c)); return d;
}
__device__ __forceinline__ float tanh_fast(float x) {   // 1 MUFU
    float y; asm("tanh.approx.f32 %0, %1;" : "=f"(y) : "f"(x)); return y;
}
__device__ __forceinline__ int rb(int x) { return x * 31 - ((x * (x - 1)) >> 1); }

__global__ __launch_bounds__(256, 3)
void magnet_main(const float* __restrict__ X,     // [S,32,4]
                 const float* __restrict__ L1W,   // [64,4]
                 const float* __restrict__ L1b,   // [64]
                 const float* __restrict__ L2W,   // [64,64]
                 const float* __restrict__ L2b,   // [64]
                 const float* __restrict__ I1W,   // [64,64]
                 const float* __restrict__ I2W,   // [8,64]
                 const float* __restrict__ I3,    // [992,2,4]
                 const float* __restrict__ S1W,   // [4,4]
                 const float* __restrict__ S1b,   // [4]
                 const float* __restrict__ S2W,   // [32,2,2]
                 const float* __restrict__ S2b,   // [32,2]
                 float* __restrict__ out)         // [S,32,2]
{
    // 2 samples per block
    __shared__ __align__(16) float bufT1[2 * SAMP_F];       // h1 [s][k][PT]; reused: a [s][obj][PA]
    __shared__ __align__(16) float bufT2_sPair[2 * SAMP_F]; // h2 [s][k][PT]; alias: sPair [s][496][4]
    __shared__ __align__(16) float sW[H_D * H_D];           // L2W then I1W (row-major [c][k])
    __shared__ __align__(16) float sI2[H_D * 8];            // [h][f]
    __shared__ __align__(16) float sX[2 * N_OBJ * 4];
    __shared__ __align__(16) float sL1W[H_D * 4];
    __shared__ float sL1b[H_D];
    __shared__ float sL2b[H_D];
    __shared__ float sRes[2 * N_OBJ * 2];

    float* bufT2 = bufT2_sPair;
    float* sPair = bufT2_sPair;

    const int tid  = threadIdx.x;
    const int bid  = blockIdx.x;
    const int wS   = tid >> 5;       // warp 0..7
    const int lane = tid & 31;       // = object in encoder stages
    const int c0   = wS * 8;         // 8 channels per warp (warp-uniform)

    // ---- staging ----
    {
        const float4* W2 = (const float4*)L2W;
        #pragma unroll
        for (int q = 0; q < 4; q++)
            ((float4*)sW)[tid + q * 256] = __ldg(W2 + tid + q * 256);
        #pragma unroll
        for (int e = 0; e < 2; e++) {                 // sI2[h][f] = I2W[f][h]
            int idx = tid + e * 256;
            int h = idx >> 3, f = idx & 7;
            sI2[idx] = __ldg(I2W + f * 64 + h);
        }
        if (tid < 64)        ((float4*)sX)[tid]        = __ldg(((const float4*)X) + bid * 64 + tid);
        else if (tid < 128)  ((float4*)sL1W)[tid - 64] = __ldg(((const float4*)L1W) + (tid - 64));
        else if (tid < 192)  sL1b[tid - 128] = __ldg(L1b + tid - 128);
        else                 sL2b[tid - 192] = __ldg(L2b + tid - 192);
    }
    __syncthreads();

    // ---- stage 1: h1 = relu(x @ L1W^T + L1b), both samples -> bufT1 transposed ----
    {
        float4 x0 = ((const float4*)sX)[lane];
        float4 x1 = ((const float4*)sX)[N_OBJ + lane];
        #pragma unroll
        for (int q = 0; q < 8; q++) {
            int c = c0 + q;
            float4 w = ((const float4*)sL1W)[c];         // broadcast (both samples)
            float b = sL1b[c];
            float v0 = fmaf(x0.x, w.x, fmaf(x0.y, w.y, fmaf(x0.z, w.z, fmaf(x0.w, w.w, b))));
            float v1 = fmaf(x1.x, w.x, fmaf(x1.y, w.y, fmaf(x1.z, w.z, fmaf(x1.w, w.w, b))));
            bufT1[c * PT + lane]          = fmaxf(v0, 0.f);
            bufT1[SAMP_F + c * PT + lane] = fmaxf(v1, 0.f);
        }
    }
    // ---- self term (64 threads = 2 samples x 32 obj) -> sRes ----
    if (tid < 64) {
        int o = tid & 31;
        float4 xv = ((const float4*)sX)[tid];
        float hs[4];
        #pragma unroll
        for (int f = 0; f < 4; f++) {
            float4 w = __ldg(((const float4*)S1W) + f);
            hs[f] = fmaxf(xv.x*w.x + xv.y*w.y + xv.z*w.z + xv.w*w.w + __ldg(S1b + f), 0.f);
        }
        float4 s2 = __ldg(((const float4*)S2W) + o);
        sRes[tid * 2 + 0] = hs[0] * s2.x + hs[1] * s2.y + __ldg(S2b + o * 2 + 0);
        sRes[tid * 2 + 1] = hs[2] * s2.z + hs[3] * s2.w + __ldg(S2b + o * 2 + 1);
    }
    __syncthreads();

    // ---- stage 2: h2 = relu(h1 @ L2W^T + L2b), both samples -> bufT2 ----
    {
        u64 acc0[8], acc1[8];
        #pragma unroll
        for (int q = 0; q < 8; q++) { acc0[q] = pack2(sL2b[c0 + q], 0.f); acc1[q] = acc0[q]; }
        #pragma unroll
        for (int k4 = 0; k4 < 16; k4++) {
            int kb = k4 * 4;
            float p0 = bufT1[(kb + 0) * PT + lane];
            float p1 = bufT1[(kb + 1) * PT + lane];
            float p2 = bufT1[(kb + 2) * PT + lane];
            float p3 = bufT1[(kb + 3) * PT + lane];
            float q0 = bufT1[SAMP_F + (kb + 0) * PT + lane];
            float q1 = bufT1[SAMP_F + (kb + 1) * PT + lane];
            float q2 = bufT1[SAMP_F + (kb + 2) * PT + lane];
            float q3 = bufT1[SAMP_F + (kb + 3) * PT + lane];
            u64 hA0 = pack2(p0, p1), hA1 = pack2(p2, p3);
            u64 hB0 = pack2(q0, q1), hB1 = pack2(q2, q3);
            #pragma unroll
            for (int q = 0; q < 8; q++) {
                ulonglong2 w = *(const ulonglong2*)&sW[(c0 + q) * 64 + kb];  // 1 bcast, 2 samples
                acc0[q] = ffma2(hA0, w.x, acc0[q]); acc0[q] = ffma2(hA1, w.y, acc0[q]);
                acc1[q] = ffma2(hB0, w.x, acc1[q]); acc1[q] = ffma2(hB1, w.y, acc1[q]);
            }
        }
        #pragma unroll
        for (int q = 0; q < 8; q++) {
            float lo, hi;
            unpack2(acc0[q], lo, hi); bufT2[(c0 + q) * PT + lane]          = fmaxf(lo + hi, 0.f);
            unpack2(acc1[q], lo, hi); bufT2[SAMP_F + (c0 + q) * PT + lane] = fmaxf(lo + hi, 0.f);
        }
    }
    __syncthreads();

    // ---- restage: sW <- I1W ----
    {
        const float4* W1 = (const float4*)I1W;
        #pragma unroll
        for (int q = 0; q < 4; q++)
            ((float4*)sW)[tid + q * 256] = __ldg(W1 + tid + q * 256);
    }
    __syncthreads();

    // ---- stage 3: a = h2 @ I1W^T -> bufT1 reused ROW-MAJOR a[s][obj][PA] ----
    {
        u64 acc0[8] = {0,0,0,0,0,0,0,0}, acc1[8] = {0,0,0,0,0,0,0,0};
        #pragma unroll
        for (int k4 = 0; k4 < 16; k4++) {
            int kb = k4 * 4;
            float p0 = bufT2[(kb + 0) * PT + lane];
            float p1 = bufT2[(kb + 1) * PT + lane];
            float p2 = bufT2[(kb + 2) * PT + lane];
            float p3 = bufT2[(kb + 3) * PT + lane];
            float q0 = bufT2[SAMP_F + (kb + 0) * PT + lane];
            float q1 = bufT2[SAMP_F + (kb + 1) * PT + lane];
            float q2 = bufT2[SAMP_F + (kb + 2) * PT + lane];
            float q3 = bufT2[SAMP_F + (kb + 3) * PT + lane];
            u64 hA0 = pack2(p0, p1), hA1 = pack2(p2, p3);
            u64 hB0 = pack2(q0, q1), hB1 = pack2(q2, q3);
            #pragma unroll
            for (int q = 0; q < 8; q++) {
                ulonglong2 w = *(const ulonglong2*)&sW[(c0 + q) * 64 + kb];
                acc0[q] = ffma2(hA0, w.x, acc0[q]); acc0[q] = ffma2(hA1, w.y, acc0[q]);
                acc1[q] = ffma2(hB0, w.x, acc1[q]); acc1[q] = ffma2(hB1, w.y, acc1[q]);
            }
        }
        float4 o; float lo, hi;
        unpack2(acc0[0], lo, hi); o.x = lo + hi;
        unpack2(acc0[1], lo, hi); o.y = lo + hi;
        unpack2(acc0[2], lo, hi); o.z = lo + hi;
        unpack2(acc0[3], lo, hi); o.w = lo + hi;
        *(float4*)&bufT1[lane * PA + c0] = o;
        unpack2(acc0[4], lo, hi); o.x = lo + hi;
        unpack2(acc0[5], lo, hi); o.y = lo + hi;
        unpack2(acc0[6], lo, hi); o.z = lo + hi;
        unpack2(acc0[7], lo, hi); o.w = lo + hi;
        *(float4*)&bufT1[lane * PA + c0 + 4] = o;
        unpack2(acc1[0], lo, hi); o.x = lo + hi;
        unpack2(acc1[1], lo, hi); o.y = lo + hi;
        unpack2(acc1[2], lo, hi); o.z = lo + hi;
        unpack2(acc1[3], lo, hi); o.w = lo + hi;
        *(float4*)&bufT1[SAMP_F + lane * PA + c0] = o;
        unpack2(acc1[4], lo, hi); o.x = lo + hi;
        unpack2(acc1[5], lo, hi); o.y = lo + hi;
        unpack2(acc1[6], lo, hi); o.z = lo + hi;
        unpack2(acc1[7], lo, hi); o.w = lo + hi;
        *(float4*)&bufT1[SAMP_F + lane * PA + c0 + 4] = o;
    }
    __syncthreads();

    // ---- pair stage: unit = (i, j0, j1), same unit for both samples ----
    {
        int i = 0, base = 0;
        while (tid >= base + ((32 - i) >> 1)) { base += (32 - i) >> 1; ++i; }
        const int u  = tid - base;
        const int nu = (32 - i) >> 1;
        const int j0 = i + 1 + u;
        const int j1 = j0 + nu;
        const bool has2 = (j1 <= 31);
        const int j1c = has2 ? j1 : j0;

        const float4* A = (const float4*)bufT1;      // rows of 17 float4; sample 1 at +544
        const float4* ai0  = A + i * 17;
        const float4* aj00 = A + j0 * 17;
        const float4* aj01 = A + j1c * 17;
        const float4* ai1  = A + 544 + i * 17;
        const float4* aj10 = A + 544 + j0 * 17;
        const float4* aj11 = A + 544 + j1c * 17;

        u64 P[4][4] = {};   // [s0p0, s0p1, s1p0, s1p1][feature-pair]
        #pragma unroll
        for (int k4 = 0; k4 < 16; k4++) {
            float4 x0 = ai0[k4], y00 = aj00[k4], y01 = aj01[k4];
            float4 x1 = ai1[k4], y10 = aj10[k4], y11 = aj11[k4];
            const float* fx0 = (const float*)&x0;
            const float* f00 = (const float*)&y00;
            const float* f01 = (const float*)&y01;
            const float* fx1 = (const float*)&x1;
            const float* f10 = (const float*)&y10;
            const float* f11 = (const float*)&y11;
            #pragma unroll
            for (int v = 0; v < 4; v++) {
                float t0 = tanh_fast(fx0[v] - f00[v]);
                float t1 = tanh_fast(fx0[v] - f01[v]);
                float t2 = tanh_fast(fx1[v] - f10[v]);
                float t3 = tanh_fast(fx1[v] - f11[v]);
                const ulonglong2* wp = (const ulonglong2*)&sI2[(k4 * 4 + v) * 8];
                ulonglong2 wa = wp[0], wb = wp[1];   // 1 bcast, 4 pair-instances
                u64 tt;
                tt = pack2(t0, t0);
                P[0][0] = ffma2(tt, wa.x, P[0][0]); P[0][1] = ffma2(tt, wa.y, P[0][1]);
                P[0][2] = ffma2(tt, wb.x, P[0][2]); P[0][3] = ffma2(tt, wb.y, P[0][3]);
                tt = pack2(t1, t1);
                P[1][0] = ffma2(tt, wa.x, P[1][0]); P[1][1] = ffma2(tt, wa.y, P[1][1]);
                P[1][2] = ffma2(tt, wb.x, P[1][2]); P[1][3] = ffma2(tt, wb.y, P[1][3]);
                tt = pack2(t2, t2);
                P[2][0] = ffma2(tt, wa.x, P[2][0]); P[2][1] = ffma2(tt, wa.y, P[2][1]);
                P[2][2] = ffma2(tt, wb.x, P[2][2]); P[2][3] = ffma2(tt, wb.y, P[2][3]);
                tt = pack2(t3, t3);
                P[3][0] = ffma2(tt, wa.x, P[3][0]); P[3][1] = ffma2(tt, wa.y, P[3][1]);
                P[3][2] = ffma2(tt, wb.x, P[3][2]); P[3][3] = ffma2(tt, wb.y, P[3][3]);
            }
        }

        const int rbi = rb(i);
        #pragma unroll
        for (int pp = 0; pp < 2; pp++) {
            if (pp == 1 && !has2) break;
            int j = pp ? j1 : j0;
            int idx_ij = i * 31 + (j - 1);
            int idx_ji = j * 31 + i;
            float4 gi0 = __ldg((const float4*)(I3 + idx_ij * 8));
            float4 gi1 = __ldg((const float4*)(I3 + idx_ij * 8) + 1);
            float4 gj0 = __ldg((const float4*)(I3 + idx_ji * 8));
            float4 gj1 = __ldg((const float4*)(I3 + idx_ji * 8) + 1);
            int p = rbi + (j - i - 1);
            #pragma unroll
            for (int s2 = 0; s2 < 2; s2++) {         // I3 loaded once, both samples
                int pi = s2 * 2 + pp;
                float t[8];
                unpack2(P[pi][0], t[0], t[1]); unpack2(P[pi][1], t[2], t[3]);
                unpack2(P[pi][2], t[4], t[5]); unpack2(P[pi][3], t[6], t[7]);
                #pragma unroll
                for (int f = 0; f < 8; f++) t[f] = tanh_fast(t[f]);
                float4 res;
                res.x = t[0]*gi0.x + t[1]*gi0.y + t[2]*gi0.z + t[3]*gi0.w;
                res.y = t[4]*gi1.x + t[5]*gi1.y + t[6]*gi1.z + t[7]*gi1.w;
                res.z = -(t[0]*gj0.x + t[1]*gj0.y + t[2]*gj0.z + t[3]*gj0.w);
                res.w = -(t[4]*gj1.x + t[5]*gj1.y + t[6]*gj1.z + t[7]*gj1.w);
                ((float4*)(sPair + s2 * NPAIR * 4))[p] = res;   // bufT2 region (dead)
            }
        }
    }
    __syncthreads();

    // ---- parallel deterministic reduction: 4 threads per (sample, object) ----
    {
        const int s2 = tid >> 7;          // sample
        const int o  = (tid >> 2) & 31;   // object
        const int q  = tid & 3;           // quarter
        const float2* sp2 = (const float2*)(sPair + s2 * NPAIR * 4);
        float a0 = 0.f, a1 = 0.f;
        const int nrow = 31 - o;          // row terms (j > o), then col terms
        for (int m = q; m < 31; m += 4) {
            int p, half;
            if (m < nrow) { p = rb(o) + m; half = 0; }
            else          { int k = m - nrow; p = rb(k) + (o - k - 1); half = 1; }
            float2 v = sp2[p * 2 + half];
            a0 += v.x; a1 += v.y;
        }
        a0 += __shfl_xor_sync(0xffffffffu, a0, 1);
        a1 += __shfl_xor_sync(0xffffffffu, a1, 1);
        a0 += __shfl_xor_sync(0xffffffffu, a0, 2);
        a1 += __shfl_xor_sync(0xffffffffu, a1, 2);
        if (q == 0) {
            float2 r;
            r.x = a0 + sRes[(s2 * N_OBJ + o) * 2 + 0];
            r.y = a1 + sRes[(s2 * N_OBJ + o) * 2 + 1];
            ((float2*)out)[(bid * 2 + s2) * N_OBJ + o] = r;
        }
    }
}

extern "C" void kernel_launch(void* const* d_in, const int* in_sizes, int n_in,
                              void* d_out, int out_size) {
    const float* inputs = (const float*)d_in[0];
    const float* L1W    = (const float*)d_in[1];
    const float* L1b    = (const float*)d_in[2];
    const float* L2W    = (const float*)d_in[3];
    const float* L2b    = (const float*)d_in[4];
    const float* I1W    = (const float*)d_in[5];
    const float* I2W    = (const float*)d_in[6];
    const float* I3     = (const float*)d_in[7];
    const float* S1W    = (const float*)d_in[8];
    const float* S1b    = (const float*)d_in[9];
    const float* S2W    = (const float*)d_in[10];
    const float* S2b    = (const float*)d_in[11];
    float* out = (float*)d_out;

    magnet_main<<<S_TOT / 2, 256>>>(inputs, L1W, L1b, L2W, L2b,
                                    I1W, I2W, I3, S1W, S1b, S2W, S2b, out);
}